// round 9
// baseline (speedup 1.0000x reference)
#include <cuda_runtime.h>
#include <cuda_bf16.h>
#include <math.h>

// ----------------------------------------------------------------------------
// BlobStore — bit-exact replication of the reference fp32 scoring chain:
//   q2_n    = sum_d fl(q_d^2) * iv[n,d]            (sequential k-ascending FFMA)
//   cross_n = sum_d q_d * fl(mu*iv)[n,d]           (sequential k-ascending FFMA)
//   mahal   = (q2 - 2*cross) + m2                  (exact jnp op order)
//   t       = -0.5 * mahal                         (exact)
//   score   = __nv_expf(t / tau) * alpha           (libdevice exp, IEEE div)
// Ranking by t is monotone in score except exp-output ties, so: coarse top-32
// by (t, idx), then exact score refinement of the 32 candidates, final top-k
// by (score desc, idx asc) == jax.lax.top_k semantics.
// Downstream: eff is hard-capped (alpha*K >> T_MAX/k), so weights are fixed
// constants; composite is insensitive to arithmetic detail.
// ----------------------------------------------------------------------------

extern "C" __device__ float __nv_expf(float);   // libdevice, immune to fast-math

typedef unsigned long long ull;

#define DS   64
#define NMAX 131072
#define BMAX 1024
#define NCAND 32

__device__ float g_Wiv[(size_t)DS * NMAX];   // iv rows, [d][n]
__device__ float g_Wmu[(size_t)DS * NMAX];   // mu*iv rows, [d][n]
__device__ float g_m2[NMAX];
__device__ float g_alpha[NMAX];
__device__ float g_Xq2[(size_t)DS * BMAX];   // fl(q^2), [d][b]
__device__ float g_Xq [(size_t)DS * BMAX];   // q, [d][b]
__device__ float g_T[(size_t)BMAX * NMAX];   // t = -0.5*mahal (512 MB)
__device__ int   g_topidx[BMAX * NCAND];
__device__ float g_topval[BMAX * NCAND];

__device__ __forceinline__ ull pk2(float lo, float hi) {
    ull r; asm("mov.b64 %0, {%1, %2};" : "=l"(r) : "f"(lo), "f"(hi)); return r;
}
__device__ __forceinline__ void upk2(ull v, float& lo, float& hi) {
    asm("mov.b64 {%0, %1}, %2;" : "=f"(lo), "=f"(hi) : "l"(v));
}
__device__ __forceinline__ void ffma2(ull& d, ull a, ull b) {
    asm("fma.rn.f32x2 %0, %1, %2, %0;" : "+l"(d) : "l"(a), "l"(b));
}

// ---------------------------------------------------------------------------
__global__ void prep_blob(const float* __restrict__ mu,
                          const float* __restrict__ lv,
                          const float* __restrict__ ra, int N) {
    int n = blockIdx.x * blockDim.x + threadIdx.x;
    if (n >= N) return;
    float m2 = 0.f;
    #pragma unroll 8
    for (int d = 0; d < DS; ++d) {
        float m  = mu[(size_t)n * DS + d];
        float iv = __nv_expf(-lv[(size_t)n * DS + d]);
        g_Wiv[(size_t)d * N + n] = iv;
        g_Wmu[(size_t)d * N + n] = __fmul_rn(m, iv);
        m2 = __fadd_rn(m2, __fmul_rn(__fmul_rn(m, m), iv));
    }
    g_m2[n] = m2;
    float x = ra[n];
    g_alpha[n] = __fdiv_rn(1.f, __fadd_rn(1.f, __nv_expf(-x)));
}

__global__ void prep_query(const float* __restrict__ q, int B) {
    int i = blockIdx.x * blockDim.x + threadIdx.x;
    if (i >= DS * B) return;
    int d = i / B, b = i - d * B;
    float v = q[(size_t)b * DS + d];
    g_Xq2[i] = __fmul_rn(v, v);
    g_Xq[i]  = v;
}

// ---------------------------------------------------------------------------
// t-GEMM: block tile 128q x 128n, thread tile 8q x 8n (f32x2 pairs), two
// sequential 64-step accumulator chains per output (bit-exact vs reference).
// ---------------------------------------------------------------------------
__global__ __launch_bounds__(256, 1)
void gemm_t_kernel(int B, int N) {
    extern __shared__ float sm[];
    float* s_q2 = sm;                 // [64][128]
    float* s_q  = sm + DS * 128;      // [64][128]
    const int tid = threadIdx.x;
    const int tx = tid & 15, ty = tid >> 4;
    const int nb = blockIdx.x * 128, qb = blockIdx.y * 128;

    for (int i = tid; i < DS * 128; i += 256) {
        int d = i >> 7, j = i & 127;
        s_q2[i] = g_Xq2[(size_t)d * B + qb + j];
        s_q[i]  = g_Xq [(size_t)d * B + qb + j];
    }
    __syncthreads();

    const int n0 = nb + tx * 8;
    ull a1[8][4], a2[8][4];
    #pragma unroll
    for (int qi = 0; qi < 8; ++qi)
        #pragma unroll
        for (int ni = 0; ni < 4; ++ni) { a1[qi][ni] = 0ull; a2[qi][ni] = 0ull; }

    const float* piv = g_Wiv + n0;
    const float* pmu = g_Wmu + n0;
    float4 w1a = *(const float4*)(piv), w1b = *(const float4*)(piv + 4);
    float4 w2a = *(const float4*)(pmu), w2b = *(const float4*)(pmu + 4);

    for (int d = 0; d < DS; ++d) {
        ull W1[4] = { pk2(w1a.x, w1a.y), pk2(w1a.z, w1a.w),
                      pk2(w1b.x, w1b.y), pk2(w1b.z, w1b.w) };
        ull W2[4] = { pk2(w2a.x, w2a.y), pk2(w2a.z, w2a.w),
                      pk2(w2b.x, w2b.y), pk2(w2b.z, w2b.w) };
        if (d + 1 < DS) {   // prefetch next W rows
            piv += N; pmu += N;
            w1a = *(const float4*)(piv); w1b = *(const float4*)(piv + 4);
            w2a = *(const float4*)(pmu); w2b = *(const float4*)(pmu + 4);
        }
        float4 qa = *(const float4*)(s_q2 + d * 128 + ty * 8);
        float4 qc = *(const float4*)(s_q2 + d * 128 + ty * 8 + 4);
        float4 pa = *(const float4*)(s_q  + d * 128 + ty * 8);
        float4 pc = *(const float4*)(s_q  + d * 128 + ty * 8 + 4);
        float vq2[8] = { qa.x, qa.y, qa.z, qa.w, qc.x, qc.y, qc.z, qc.w };
        float vq [8] = { pa.x, pa.y, pa.z, pa.w, pc.x, pc.y, pc.z, pc.w };
        #pragma unroll
        for (int qi = 0; qi < 8; ++qi) {
            ull bq2 = pk2(vq2[qi], vq2[qi]);
            ull bq  = pk2(vq[qi],  vq[qi]);
            #pragma unroll
            for (int ni = 0; ni < 4; ++ni) {
                ffma2(a1[qi][ni], bq2, W1[ni]);
                ffma2(a2[qi][ni], bq,  W2[ni]);
            }
        }
    }

    float m2v[8];
    { float4 ma = *(const float4*)(g_m2 + n0);
      float4 mb = *(const float4*)(g_m2 + n0 + 4);
      m2v[0]=ma.x; m2v[1]=ma.y; m2v[2]=ma.z; m2v[3]=ma.w;
      m2v[4]=mb.x; m2v[5]=mb.y; m2v[6]=mb.z; m2v[7]=mb.w; }

    #pragma unroll
    for (int qi = 0; qi < 8; ++qi) {
        float o[8];
        #pragma unroll
        for (int ni = 0; ni < 4; ++ni) {
            float x1l, x1h, x2l, x2h;
            upk2(a1[qi][ni], x1l, x1h);
            upk2(a2[qi][ni], x2l, x2h);
            // t = -0.5 * ((q2 - 2*cross) + m2)   — exact jnp op order
            o[2*ni]   = __fmul_rn(-0.5f, __fadd_rn(__fsub_rn(x1l, __fmul_rn(2.0f, x2l)), m2v[2*ni]));
            o[2*ni+1] = __fmul_rn(-0.5f, __fadd_rn(__fsub_rn(x1h, __fmul_rn(2.0f, x2h)), m2v[2*ni+1]));
        }
        size_t row = (size_t)(qb + ty * 8 + qi);
        float4* dst = (float4*)(g_T + row * N + n0);
        dst[0] = make_float4(o[0], o[1], o[2], o[3]);
        dst[1] = make_float4(o[4], o[5], o[6], o[7]);
    }
}

// ---------------------------------------------------------------------------
// Top-32 by (t desc, idx asc): per-thread sorted-16 scan, block merge 32 rounds.
// ---------------------------------------------------------------------------
__device__ __forceinline__ void insert16(float* val, int* idx, float s, int n) {
    float cv = s; int ci = n;
    #pragma unroll
    for (int j = 0; j < 16; ++j) {
        bool better = (cv > val[j]) || (cv == val[j] && ci < idx[j]);
        if (better) {
            float tv = val[j]; val[j] = cv; cv = tv;
            int   ti = idx[j]; idx[j] = ci; ci = ti;
        }
    }
}

__global__ __launch_bounds__(256)
void topk_kernel(int B, int N) {
    const int b = blockIdx.x;
    const int tid = threadIdx.x;
    const float* row = g_T + (size_t)b * N;

    float val[16]; int idx[16];
    #pragma unroll
    for (int j = 0; j < 16; ++j) { val[j] = -INFINITY; idx[j] = 0x7fffffff; }

    for (int base = tid * 4; base < N; base += 1024) {
        float4 v = *(const float4*)(row + base);
        if (v.x > val[15] || (v.x == val[15] && base + 0 < idx[15])) insert16(val, idx, v.x, base + 0);
        if (v.y > val[15] || (v.y == val[15] && base + 1 < idx[15])) insert16(val, idx, v.y, base + 1);
        if (v.z > val[15] || (v.z == val[15] && base + 2 < idx[15])) insert16(val, idx, v.z, base + 2);
        if (v.w > val[15] || (v.w == val[15] && base + 3 < idx[15])) insert16(val, idx, v.w, base + 3);
    }

    __shared__ float sval[4096];
    __shared__ int   sidx[4096];
    __shared__ float rv[8];
    __shared__ int   ri[8], rs[8];
    #pragma unroll
    for (int j = 0; j < 16; ++j) { sval[tid * 16 + j] = val[j]; sidx[tid * 16 + j] = idx[j]; }
    __syncthreads();

    for (int r = 0; r < NCAND; ++r) {
        float bv = -INFINITY; int bi = 0x7fffffff, bs = -1;
        for (int j = tid; j < 4096; j += 256) {
            float v = sval[j]; int id = sidx[j];
            if (v > bv || (v == bv && id < bi)) { bv = v; bi = id; bs = j; }
        }
        #pragma unroll
        for (int off = 16; off; off >>= 1) {
            float ov = __shfl_down_sync(0xffffffffu, bv, off);
            int   oi = __shfl_down_sync(0xffffffffu, bi, off);
            int   os = __shfl_down_sync(0xffffffffu, bs, off);
            if (ov > bv || (ov == bv && oi < bi)) { bv = ov; bi = oi; bs = os; }
        }
        if ((tid & 31) == 0) { rv[tid >> 5] = bv; ri[tid >> 5] = bi; rs[tid >> 5] = bs; }
        __syncthreads();
        if (tid == 0) {
            float fbv = rv[0]; int fbi = ri[0], fbs = rs[0];
            #pragma unroll
            for (int w = 1; w < 8; ++w)
                if (rv[w] > fbv || (rv[w] == fbv && ri[w] < fbi)) { fbv = rv[w]; fbi = ri[w]; fbs = rs[w]; }
            g_topidx[b * NCAND + r] = fbi;
            g_topval[b * NCAND + r] = fbv;
            sval[fbs] = -INFINITY;
            sidx[fbs] = 0x7fffffff;
        }
        __syncthreads();
    }
}

// ---------------------------------------------------------------------------
// Refine 32 candidates with the exact reference score, pick k, rescore,
// composite, feature reduction, t_residual.
// ---------------------------------------------------------------------------
__global__ __launch_bounds__(256)
void composite_kernel(const float* __restrict__ q,
                      const float* __restrict__ mu,
                      const float* __restrict__ lv,
                      const float* __restrict__ ra,
                      const float* __restrict__ feat,
                      const float* __restrict__ lt,
                      const int* __restrict__ kptr,
                      float* __restrict__ out,
                      int B, int dF, int out_size) {
    const int b = blockIdx.x;
    const int tid = threadIdx.x;
    const int warp = tid >> 5, lane = tid & 31;

    __shared__ float cs[NCAND];
    __shared__ int   ci[NCAND];
    __shared__ int   s_ord[16];
    __shared__ float s_eff[16];
    __shared__ float s_w[16];
    __shared__ float s_tres;

    int kk = kptr ? *kptr : 16;
    if (kk > 16) kk = 16;
    if (kk < 1)  kk = 1;
    float tau = __nv_expf(lt[0]);
    float cap = (float)(0.3 / (double)kk);   // T_MAX / k

    if (tid < NCAND) {
        int   id = g_topidx[b * NCAND + tid];
        float t  = g_topval[b * NCAND + tid];
        // score = expf(t / tau) * alpha  — exact reference chain
        cs[tid] = __fmul_rn(__nv_expf(__fdiv_rn(t, tau)), g_alpha[id]);
        ci[tid] = id;
    }
    __syncthreads();

    if (tid == 0) {
        // selection sort by (score desc, idx asc) — jax.lax.top_k semantics
        for (int r = 0; r < kk; ++r) {
            int best = r;
            for (int j = r + 1; j < NCAND; ++j)
                if (cs[j] > cs[best] || (cs[j] == cs[best] && ci[j] < ci[best])) best = j;
            float tv = cs[r]; cs[r] = cs[best]; cs[best] = tv;
            int   ti = ci[r]; ci[r] = ci[best]; ci[best] = ti;
            s_ord[r] = ci[r];
        }
    }
    __syncthreads();

    // Exact rescore (eff is capped with huge margin; arithmetic detail is moot)
    for (int i = warp; i < kk; i += 8) {
        int n = s_ord[i];
        float d0 = q[(size_t)b * DS + lane]      - mu[(size_t)n * DS + lane];
        float d1 = q[(size_t)b * DS + lane + 32] - mu[(size_t)n * DS + lane + 32];
        float iv0 = __nv_expf(-lv[(size_t)n * DS + lane]);
        float iv1 = __nv_expf(-lv[(size_t)n * DS + lane + 32]);
        float s = d0 * d0 * iv0 + d1 * d1 * iv1;
        #pragma unroll
        for (int off = 16; off; off >>= 1) s += __shfl_xor_sync(0xffffffffu, s, off);
        if (lane == 0) {
            float K = __nv_expf(__fdiv_rn(-0.5f * s, tau));
            float a = __fdiv_rn(1.f, 1.f + __nv_expf(-ra[n]));
            s_eff[i] = fminf(a * K, cap);
        }
    }
    __syncthreads();

    if (tid == 0) {
        float logT = 0.f;
        for (int i = 0; i < kk; ++i) {
            float e = s_eff[i];
            s_w[i] = e * __nv_expf(logT);
            logT += log1pf(-fminf(e, 1.f - 1e-6f));
        }
        s_tres = __nv_expf(logT);
    }
    __syncthreads();

    for (int d = tid; d < dF; d += 256) {
        float acc = 0.f;
        for (int i = 0; i < kk; ++i)
            acc += s_w[i] * feat[(size_t)s_ord[i] * dF + d];
        out[(size_t)b * dF + d] = acc;
    }
    if (tid == 0 && out_size >= B * dF + B)
        out[(size_t)B * dF + b] = s_tres;
}

// ---------------------------------------------------------------------------
extern "C" void kernel_launch(void* const* d_in, const int* in_sizes, int n_in,
                              void* d_out, int out_size) {
    const float* query     = (const float*)d_in[0];
    const float* mu        = (const float*)d_in[1];
    const float* log_var   = (const float*)d_in[2];
    const float* raw_alpha = (const float*)d_in[3];
    const float* features  = (const float*)d_in[4];
    const float* log_tau   = (const float*)d_in[5];
    const int*   kptr      = (n_in >= 7) ? (const int*)d_in[6] : nullptr;

    int B  = in_sizes[0] / DS;     // 1024
    int N  = in_sizes[1] / DS;     // 131072
    int dF = in_sizes[4] / N;      // 256
    float* out = (float*)d_out;

    prep_blob<<<(N + 255) / 256, 256>>>(mu, log_var, raw_alpha, N);
    prep_query<<<(DS * B + 255) / 256, 256>>>(query, B);

    static bool attr_set = false;
    if (!attr_set) {
        cudaFuncSetAttribute(gemm_t_kernel,
                             cudaFuncAttributeMaxDynamicSharedMemorySize, 65536);
        attr_set = true;
    }
    dim3 ggrid(N / 128, B / 128);
    gemm_t_kernel<<<ggrid, 256, 65536>>>(B, N);

    topk_kernel<<<B, 256>>>(B, N);

    composite_kernel<<<B, 256>>>(query, mu, log_var, raw_alpha, features,
                                 log_tau, kptr, out, B, dF, out_size);
}

// round 11
// speedup vs baseline: 1.1156x; 1.1156x over previous
#include <cuda_runtime.h>
#include <cuda_bf16.h>
#include <math.h>

// ----------------------------------------------------------------------------
// BlobStore — bit-exact replication of the reference fp32 scoring chain:
//   q2_n    = sum_d fl(q_d^2) * iv[n,d]            (sequential d-ascending FFMA)
//   cross_n = sum_d q_d * fl(mu*iv)[n,d]           (sequential d-ascending FFMA)
//   mahal   = (q2 - 2*cross) + m2                  (exact jnp op order)
//   t       = -0.5 * mahal
//   score   = __nv_expf(t / tau) * alpha
// Coarse top-32 by (t desc, idx asc), exact-score refinement, top-k by
// (score desc, idx asc) == jax.lax.top_k. eff is hard-capped downstream so
// the composite is insensitive to rounding.
//
// R10 changes vs R9 (which passed at 2938us):
//   * GEMM re-tiled 4q x 8n per thread (64 acc regs, no spill), W loaded as
//     ulonglong2 directly (f32x2 lane order == memory order), launch_bounds
//     (256,2), static 32KB smem, L2-friendly grid order.
//   * prep_blob fully coalesced via smem transpose (identical arithmetic).
// ----------------------------------------------------------------------------

extern "C" __device__ float __nv_expf(float);   // libdevice, immune to fast-math

typedef unsigned long long ull;

#define DS   64
#define NMAX 131072
#define BMAX 1024
#define NCAND 32

__device__ float g_Wiv[(size_t)DS * NMAX];   // iv rows, [d][n]
__device__ float g_Wmu[(size_t)DS * NMAX];   // mu*iv rows, [d][n]
__device__ float g_m2[NMAX];
__device__ float g_alpha[NMAX];
__device__ float g_Xq2[(size_t)DS * BMAX];   // fl(q^2), [d][b]
__device__ float g_Xq [(size_t)DS * BMAX];   // q, [d][b]
__device__ float g_T[(size_t)BMAX * NMAX];   // t = -0.5*mahal (512 MB)
__device__ int   g_topidx[BMAX * NCAND];
__device__ float g_topval[BMAX * NCAND];

__device__ __forceinline__ ull pk2(float lo, float hi) {
    ull r; asm("mov.b64 %0, {%1, %2};" : "=l"(r) : "f"(lo), "f"(hi)); return r;
}
__device__ __forceinline__ void upk2(ull v, float& lo, float& hi) {
    asm("mov.b64 {%0, %1}, %2;" : "=f"(lo), "=f"(hi) : "l"(v));
}
__device__ __forceinline__ void ffma2(ull& d, ull a, ull b) {
    asm("fma.rn.f32x2 %0, %1, %2, %0;" : "+l"(d) : "l"(a), "l"(b));
}

// ---------------------------------------------------------------------------
// prep_blob: coalesced read + smem transpose + coalesced column writes.
// Arithmetic identical to R9 (expf, __fmul_rn, sequential-d m2 chain).
// ---------------------------------------------------------------------------
#define PB_TILE 32
__global__ __launch_bounds__(256)
void prep_blob(const float* __restrict__ mu,
               const float* __restrict__ lv,
               const float* __restrict__ ra, int N) {
    __shared__ float s_iv [PB_TILE][DS + 1];
    __shared__ float s_miv[PB_TILE][DS + 1];
    __shared__ float s_m2t[PB_TILE][DS + 1];
    const int n0 = blockIdx.x * PB_TILE;
    const int tid = threadIdx.x;

    for (int i = tid; i < PB_TILE * DS; i += 256) {
        int nl = i >> 6, d = i & 63;
        float m  = mu[(size_t)(n0 + nl) * DS + d];
        float iv = __nv_expf(-lv[(size_t)(n0 + nl) * DS + d]);
        s_iv[nl][d]  = iv;
        s_miv[nl][d] = __fmul_rn(m, iv);
        s_m2t[nl][d] = __fmul_rn(__fmul_rn(m, m), iv);
    }
    __syncthreads();

    if (tid < PB_TILE) {
        float m2 = 0.f;
        #pragma unroll 8
        for (int d = 0; d < DS; ++d) m2 = __fadd_rn(m2, s_m2t[tid][d]);
        g_m2[n0 + tid] = m2;
        float x = ra[n0 + tid];
        g_alpha[n0 + tid] = __fdiv_rn(1.f, __fadd_rn(1.f, __nv_expf(-x)));
    }
    __syncthreads();

    for (int i = tid; i < PB_TILE * DS; i += 256) {
        int d = i >> 5, nl = i & 31;
        g_Wiv[(size_t)d * N + n0 + nl] = s_iv[nl][d];
        g_Wmu[(size_t)d * N + n0 + nl] = s_miv[nl][d];
    }
}

__global__ void prep_query(const float* __restrict__ q, int B) {
    int i = blockIdx.x * blockDim.x + threadIdx.x;
    if (i >= DS * B) return;
    int d = i / B, b = i - d * B;
    float v = q[(size_t)b * DS + d];
    g_Xq2[i] = __fmul_rn(v, v);
    g_Xq[i]  = v;
}

// ---------------------------------------------------------------------------
// t-GEMM: block tile 64q x 128n, thread tile 4q x 8n. Two sequential 64-step
// f32x2 accumulator chains per output (bit-exact vs reference). 64 acc regs.
// grid = (q-tiles, n-tiles) so a wave shares W columns across 16 q-tiles.
// ---------------------------------------------------------------------------
__global__ __launch_bounds__(256, 2)
void gemm_t_kernel(int B, int N) {
    __shared__ float s_q2[DS * 64];
    __shared__ float s_q [DS * 64];
    const int tid = threadIdx.x;
    const int tx = tid & 15, ty = tid >> 4;
    const int qb = blockIdx.x * 64, nb = blockIdx.y * 128;

    for (int i = tid; i < DS * 64; i += 256) {
        int d = i >> 6, j = i & 63;
        s_q2[i] = g_Xq2[(size_t)d * B + qb + j];
        s_q[i]  = g_Xq [(size_t)d * B + qb + j];
    }
    __syncthreads();

    const int n0 = nb + tx * 8;
    ull a1[4][4], a2[4][4];
    #pragma unroll
    for (int qi = 0; qi < 4; ++qi)
        #pragma unroll
        for (int ni = 0; ni < 4; ++ni) { a1[qi][ni] = 0ull; a2[qi][ni] = 0ull; }

    const float* piv = g_Wiv + n0;
    const float* pmu = g_Wmu + n0;
    // W loaded directly as ulonglong2: lane order == memory order for f32x2.
    ulonglong2 w1a = *(const ulonglong2*)(piv), w1b = *(const ulonglong2*)(piv + 4);
    ulonglong2 w2a = *(const ulonglong2*)(pmu), w2b = *(const ulonglong2*)(pmu + 4);

    #pragma unroll 2
    for (int d = 0; d < DS; ++d) {
        ull W1[4] = { w1a.x, w1a.y, w1b.x, w1b.y };
        ull W2[4] = { w2a.x, w2a.y, w2b.x, w2b.y };
        if (d + 1 < DS) {   // prefetch next W rows
            piv += N; pmu += N;
            w1a = *(const ulonglong2*)(piv); w1b = *(const ulonglong2*)(piv + 4);
            w2a = *(const ulonglong2*)(pmu); w2b = *(const ulonglong2*)(pmu + 4);
        }
        float4 qa = *(const float4*)(s_q2 + d * 64 + ty * 4);
        float4 pa = *(const float4*)(s_q  + d * 64 + ty * 4);
        float vq2[4] = { qa.x, qa.y, qa.z, qa.w };
        float vq [4] = { pa.x, pa.y, pa.z, pa.w };
        #pragma unroll
        for (int qi = 0; qi < 4; ++qi) {
            ull bq2 = pk2(vq2[qi], vq2[qi]);
            ull bq  = pk2(vq[qi],  vq[qi]);
            #pragma unroll
            for (int ni = 0; ni < 4; ++ni) {
                ffma2(a1[qi][ni], bq2, W1[ni]);
                ffma2(a2[qi][ni], bq,  W2[ni]);
            }
        }
    }

    float m2v[8];
    { float4 ma = *(const float4*)(g_m2 + n0);
      float4 mb = *(const float4*)(g_m2 + n0 + 4);
      m2v[0]=ma.x; m2v[1]=ma.y; m2v[2]=ma.z; m2v[3]=ma.w;
      m2v[4]=mb.x; m2v[5]=mb.y; m2v[6]=mb.z; m2v[7]=mb.w; }

    #pragma unroll
    for (int qi = 0; qi < 4; ++qi) {
        float o[8];
        #pragma unroll
        for (int ni = 0; ni < 4; ++ni) {
            float x1l, x1h, x2l, x2h;
            upk2(a1[qi][ni], x1l, x1h);
            upk2(a2[qi][ni], x2l, x2h);
            // t = -0.5 * ((q2 - 2*cross) + m2)   — exact jnp op order
            o[2*ni]   = __fmul_rn(-0.5f, __fadd_rn(__fsub_rn(x1l, __fmul_rn(2.0f, x2l)), m2v[2*ni]));
            o[2*ni+1] = __fmul_rn(-0.5f, __fadd_rn(__fsub_rn(x1h, __fmul_rn(2.0f, x2h)), m2v[2*ni+1]));
        }
        size_t row = (size_t)(qb + ty * 4 + qi);
        float4* dst = (float4*)(g_T + row * N + n0);
        dst[0] = make_float4(o[0], o[1], o[2], o[3]);
        dst[1] = make_float4(o[4], o[5], o[6], o[7]);
    }
}

// ---------------------------------------------------------------------------
// Top-32 by (t desc, idx asc): per-thread sorted-16 scan, block merge.
// ---------------------------------------------------------------------------
__device__ __forceinline__ void insert16(float* val, int* idx, float s, int n) {
    float cv = s; int ci = n;
    #pragma unroll
    for (int j = 0; j < 16; ++j) {
        bool better = (cv > val[j]) || (cv == val[j] && ci < idx[j]);
        if (better) {
            float tv = val[j]; val[j] = cv; cv = tv;
            int   ti = idx[j]; idx[j] = ci; ci = ti;
        }
    }
}

__global__ __launch_bounds__(256)
void topk_kernel(int B, int N) {
    const int b = blockIdx.x;
    const int tid = threadIdx.x;
    const float* row = g_T + (size_t)b * N;

    float val[16]; int idx[16];
    #pragma unroll
    for (int j = 0; j < 16; ++j) { val[j] = -INFINITY; idx[j] = 0x7fffffff; }

    for (int base = tid * 4; base < N; base += 1024) {
        float4 v = *(const float4*)(row + base);
        if (v.x > val[15] || (v.x == val[15] && base + 0 < idx[15])) insert16(val, idx, v.x, base + 0);
        if (v.y > val[15] || (v.y == val[15] && base + 1 < idx[15])) insert16(val, idx, v.y, base + 1);
        if (v.z > val[15] || (v.z == val[15] && base + 2 < idx[15])) insert16(val, idx, v.z, base + 2);
        if (v.w > val[15] || (v.w == val[15] && base + 3 < idx[15])) insert16(val, idx, v.w, base + 3);
    }

    __shared__ float sval[4096];
    __shared__ int   sidx[4096];
    __shared__ float rv[8];
    __shared__ int   ri[8], rs[8];
    #pragma unroll
    for (int j = 0; j < 16; ++j) { sval[tid * 16 + j] = val[j]; sidx[tid * 16 + j] = idx[j]; }
    __syncthreads();

    for (int r = 0; r < NCAND; ++r) {
        float bv = -INFINITY; int bi = 0x7fffffff, bs = -1;
        for (int j = tid; j < 4096; j += 256) {
            float v = sval[j]; int id = sidx[j];
            if (v > bv || (v == bv && id < bi)) { bv = v; bi = id; bs = j; }
        }
        #pragma unroll
        for (int off = 16; off; off >>= 1) {
            float ov = __shfl_down_sync(0xffffffffu, bv, off);
            int   oi = __shfl_down_sync(0xffffffffu, bi, off);
            int   os = __shfl_down_sync(0xffffffffu, bs, off);
            if (ov > bv || (ov == bv && oi < bi)) { bv = ov; bi = oi; bs = os; }
        }
        if ((tid & 31) == 0) { rv[tid >> 5] = bv; ri[tid >> 5] = bi; rs[tid >> 5] = bs; }
        __syncthreads();
        if (tid == 0) {
            float fbv = rv[0]; int fbi = ri[0], fbs = rs[0];
            #pragma unroll
            for (int w = 1; w < 8; ++w)
                if (rv[w] > fbv || (rv[w] == fbv && ri[w] < fbi)) { fbv = rv[w]; fbi = ri[w]; fbs = rs[w]; }
            g_topidx[b * NCAND + r] = fbi;
            g_topval[b * NCAND + r] = fbv;
            sval[fbs] = -INFINITY;
            sidx[fbs] = 0x7fffffff;
        }
        __syncthreads();
    }
}

// ---------------------------------------------------------------------------
// Refine 32 candidates with the exact reference score, pick k, rescore,
// composite, feature reduction, t_residual.
// ---------------------------------------------------------------------------
__global__ __launch_bounds__(256)
void composite_kernel(const float* __restrict__ q,
                      const float* __restrict__ mu,
                      const float* __restrict__ lv,
                      const float* __restrict__ ra,
                      const float* __restrict__ feat,
                      const float* __restrict__ lt,
                      const int* __restrict__ kptr,
                      float* __restrict__ out,
                      int B, int dF, int out_size) {
    const int b = blockIdx.x;
    const int tid = threadIdx.x;
    const int warp = tid >> 5, lane = tid & 31;

    __shared__ float cs[NCAND];
    __shared__ int   ci[NCAND];
    __shared__ int   s_ord[16];
    __shared__ float s_eff[16];
    __shared__ float s_w[16];
    __shared__ float s_tres;

    int kk = kptr ? *kptr : 16;
    if (kk > 16) kk = 16;
    if (kk < 1)  kk = 1;
    float tau = __nv_expf(lt[0]);
    float cap = (float)(0.3 / (double)kk);   // T_MAX / k

    if (tid < NCAND) {
        int   id = g_topidx[b * NCAND + tid];
        float t  = g_topval[b * NCAND + tid];
        cs[tid] = __fmul_rn(__nv_expf(__fdiv_rn(t, tau)), g_alpha[id]);
        ci[tid] = id;
    }
    __syncthreads();

    if (tid == 0) {
        for (int r = 0; r < kk; ++r) {
            int best = r;
            for (int j = r + 1; j < NCAND; ++j)
                if (cs[j] > cs[best] || (cs[j] == cs[best] && ci[j] < ci[best])) best = j;
            float tv = cs[r]; cs[r] = cs[best]; cs[best] = tv;
            int   ti = ci[r]; ci[r] = ci[best]; ci[best] = ti;
            s_ord[r] = ci[r];
        }
    }
    __syncthreads();

    for (int i = warp; i < kk; i += 8) {
        int n = s_ord[i];
        float d0 = q[(size_t)b * DS + lane]      - mu[(size_t)n * DS + lane];
        float d1 = q[(size_t)b * DS + lane + 32] - mu[(size_t)n * DS + lane + 32];
        float iv0 = __nv_expf(-lv[(size_t)n * DS + lane]);
        float iv1 = __nv_expf(-lv[(size_t)n * DS + lane + 32]);
        float s = d0 * d0 * iv0 + d1 * d1 * iv1;
        #pragma unroll
        for (int off = 16; off; off >>= 1) s += __shfl_xor_sync(0xffffffffu, s, off);
        if (lane == 0) {
            float K = __nv_expf(__fdiv_rn(-0.5f * s, tau));
            float a = __fdiv_rn(1.f, 1.f + __nv_expf(-ra[n]));
            s_eff[i] = fminf(a * K, cap);
        }
    }
    __syncthreads();

    if (tid == 0) {
        float logT = 0.f;
        for (int i = 0; i < kk; ++i) {
            float e = s_eff[i];
            s_w[i] = e * __nv_expf(logT);
            logT += log1pf(-fminf(e, 1.f - 1e-6f));
        }
        s_tres = __nv_expf(logT);
    }
    __syncthreads();

    for (int d = tid; d < dF; d += 256) {
        float acc = 0.f;
        for (int i = 0; i < kk; ++i)
            acc += s_w[i] * feat[(size_t)s_ord[i] * dF + d];
        out[(size_t)b * dF + d] = acc;
    }
    if (tid == 0 && out_size >= B * dF + B)
        out[(size_t)B * dF + b] = s_tres;
}

// ---------------------------------------------------------------------------
extern "C" void kernel_launch(void* const* d_in, const int* in_sizes, int n_in,
                              void* d_out, int out_size) {
    const float* query     = (const float*)d_in[0];
    const float* mu        = (const float*)d_in[1];
    const float* log_var   = (const float*)d_in[2];
    const float* raw_alpha = (const float*)d_in[3];
    const float* features  = (const float*)d_in[4];
    const float* log_tau   = (const float*)d_in[5];
    const int*   kptr      = (n_in >= 7) ? (const int*)d_in[6] : nullptr;

    int B  = in_sizes[0] / DS;     // 1024
    int N  = in_sizes[1] / DS;     // 131072
    int dF = in_sizes[4] / N;      // 256
    float* out = (float*)d_out;

    prep_blob<<<N / PB_TILE, 256>>>(mu, log_var, raw_alpha, N);
    prep_query<<<(DS * B + 255) / 256, 256>>>(query, B);

    dim3 ggrid(B / 64, N / 128);   // q-tiles fast => W reuse in L2
    gemm_t_kernel<<<ggrid, 256>>>(B, N);

    topk_kernel<<<B, 256>>>(B, N);

    composite_kernel<<<B, 256>>>(query, mu, log_var, raw_alpha, features,
                                 log_tau, kptr, out, B, dF, out_size);
}